// round 16
// baseline (speedup 1.0000x reference)
#include <cuda_runtime.h>

#define CN    64
#define HH    256
#define HWSZ  65536
#define NCLS  6
#define NWIN  1024

typedef unsigned long long u64;

__device__ __forceinline__ u64 pk2(float lo, float hi) {
    u64 r; asm("mov.b64 %0, {%1, %2};" : "=l"(r) : "f"(lo), "f"(hi)); return r;
}
__device__ __forceinline__ u64 bc2(float v) { return pk2(v, v); }
__device__ __forceinline__ void fma2(u64& a, u64 x, u64 y) {
    asm("fma.rn.f32x2 %0, %1, %2, %0;" : "+l"(a) : "l"(x), "l"(y));
}
__device__ __forceinline__ void mul2(u64& a, u64 x) {
    asm("mul.rn.f32x2 %0, %0, %1;" : "+l"(a) : "l"(x));
}
__device__ __forceinline__ float2 upk(u64 v) {
    float2 r; asm("mov.b64 {%0, %1}, %2;" : "=f"(r.x), "=f"(r.y) : "l"(v)); return r;
}
__device__ __forceinline__ void cpasync16(unsigned dst, const void* src) {
    asm volatile("cp.async.cg.shared.global [%0], [%1], 16;" :: "r"(dst), "l"(src));
}
__device__ __forceinline__ void cpcommit() {
    asm volatile("cp.async.commit_group;");
}
__device__ __forceinline__ void cpwait0() {
    asm volatile("cp.async.wait_group 0;" ::: "memory");
}

// ---------------- scratch (device globals; no allocations allowed) ----------
__device__ float g_mask[NCLS * NWIN * 64];
__device__ float g_qk[(size_t)NCLS * NWIN * 8192];    // per-window q (4096) + k (4096)
__device__ float g_wT[NCLS * 6 * 576 * 64];           // transposed conv weights [cm][tap][oc]
__device__ float g_out1[(size_t)NCLS * CN * HWSZ];    // x + class_attn
__device__ float g_x112[(size_t)NCLS * CN * HWSZ];
__device__ float g_x223[(size_t)NCLS * CN * HWSZ];

// ---------------------------------------------------------------------------
// K0: transpose conv weights -> [cls*6+m][tap(ic*9+ky*3+kx)][oc]
// ---------------------------------------------------------------------------
__global__ void k_prep(const float* __restrict__ w) {
    int id = blockIdx.x * 256 + threadIdx.x;
    if (id >= NCLS * 6 * 64 * 576) return;
    int cm = id / (64 * 576);
    int rem = id - cm * 64 * 576;
    int oc = rem / 576, tap = rem - oc * 576;
    g_wT[(cm * 576 + tap) * 64 + oc] = w[id];
}

// ---------------------------------------------------------------------------
// K1: qk conv in two 64-oc phases (R12 exact).
// ---------------------------------------------------------------------------
__global__ __launch_bounds__(256, 3)
void k_mask(const float* __restrict__ x, const float* __restrict__ qkw,
            const float* __restrict__ qks, const float* __restrict__ qkb,
            const float* __restrict__ relb) {
    int cls = blockIdx.y, win = blockIdx.x;
    int wy = win >> 5, wx = win & 31;
    extern __shared__ float sm[];
    float* xw   = sm;            // 4096
    float* wsm  = xw + 4096;     // 4160 (reused per phase)
    float* qk   = wsm + 4160;    // 8320
    float* qsum = qk + 8320;     // 64
    float* rsm  = qsum + 64;     // 900
    int tid = threadIdx.x;
    const float* xb = x + ((size_t)cls * CN) * HWSZ;

    for (int id = tid; id < 512; id += 256) {
        int ch = id >> 3, i = id & 7;
        const float* p = xb + (size_t)ch * HWSZ + (wy * 8 + i) * HH + wx * 8;
        float4 a = *(const float4*)p;
        float4 b = *(const float4*)(p + 4);
        float* d = xw + ch * 64 + i * 8;
        d[0]=a.x; d[1]=a.y; d[2]=a.z; d[3]=a.w;
        d[4]=b.x; d[5]=b.y; d[6]=b.z; d[7]=b.w;
    }
    const float* rb = relb + cls * 900;
    for (int id = tid; id < 900; id += 256) rsm[id] = rb[id];

    const float* sS = qks + cls * 128;
    const float* sB = qkb + cls * 128;
    int ocp = tid >> 3;
    int px0 = (tid & 7) * 8;

    #pragma unroll
    for (int ph = 0; ph < 2; ph++) {
        __syncthreads();
        const float* wb = qkw + (size_t)cls * 8192 + ph * 4096;
        for (int id = tid; id < 4096; id += 256)
            wsm[(id >> 6) * 65 + (id & 63)] = wb[id];
        __syncthreads();

        u64 acc[2][4];
        #pragma unroll
        for (int r = 0; r < 2; r++)
            #pragma unroll
            for (int j = 0; j < 4; j++) acc[r][j] = 0ull;
        const float* w0r = wsm + (2 * ocp) * 65;
        const float* w1r = wsm + (2 * ocp + 1) * 65;
        #pragma unroll 4
        for (int c = 0; c < 64; c++) {
            u64 wa = bc2(w0r[c]);
            u64 wb2 = bc2(w1r[c]);
            const ulonglong2* xp = (const ulonglong2*)(xw + c * 64 + px0);
            ulonglong2 x0 = xp[0], x1 = xp[1];
            fma2(acc[0][0], wa,  x0.x); fma2(acc[1][0], wb2, x0.x);
            fma2(acc[0][1], wa,  x0.y); fma2(acc[1][1], wb2, x0.y);
            fma2(acc[0][2], wa,  x1.x); fma2(acc[1][2], wb2, x1.x);
            fma2(acc[0][3], wa,  x1.y); fma2(acc[1][3], wb2, x1.y);
        }
        #pragma unroll
        for (int r = 0; r < 2; r++) {
            int ocl = 2 * ocp + r;
            int oc = ph * 64 + ocl;
            float s = sS[oc], b = sB[oc];
            #pragma unroll
            for (int j = 0; j < 4; j++) {
                float2 v = upk(acc[r][j]);
                qk[oc * 65 + px0 + 2 * j]     = fmaxf(v.x * s + b, 0.f);
                qk[oc * 65 + px0 + 2 * j + 1] = fmaxf(v.y * s + b, 0.f);
            }
        }
    }
    __syncthreads();

    float* gbase = g_qk + (size_t)(cls * NWIN + win) * 8192;
    for (int id = tid; id < 4096; id += 256)
        gbase[id] = qk[(id >> 6) * 65 + (id & 63)];
    for (int id = tid; id < 4096; id += 256) {
        int h = id >> 10, rem = id & 1023, px = rem >> 4, d = rem & 15;
        gbase[4096 + id] = qk[(64 + h * 16 + d) * 65 + px];
    }
    if (tid < 64) {
        float s = 0.f;
        const float* r = qk + tid * 65;
        #pragma unroll 16
        for (int p = 0; p < 64; p++) s += r[p];
        qsum[tid] = s;
    }
    __syncthreads();

    if (tid < 64) {
        int kp = tid, ik = kp >> 3, jk = kp & 7;
        float dot = 0.f;
        #pragma unroll 16
        for (int ch = 0; ch < 64; ch++) dot += qsum[ch] * qk[(64 + ch) * 65 + kp];
        float rbv = 0.f;
        for (int q = 0; q < 64; q++) {
            int ridx = ((q >> 3) - ik + 7) * 15 + ((q & 7) - jk + 7);
            const float* r4 = rsm + ridx * 4;
            rbv += r4[0] + r4[1] + r4[2] + r4[3];
        }
        g_mask[(cls * NWIN + win) * 64 + kp] = dot * (0.25f / 256.f) + rbv * (1.f / 256.f);
    }
}

// ---------------------------------------------------------------------------
// K3: attention, online-softmax single pass (R12 exact) with the cross-class
// good-mask computed inline (k_good kernel folded in).
// ---------------------------------------------------------------------------
__global__ __launch_bounds__(256, 3)
void k_attn(const float* __restrict__ x, const float* __restrict__ relb,
            const float* __restrict__ wvw, const float* __restrict__ wvs,
            const float* __restrict__ wvb) {
    int cls = blockIdx.y, win = blockIdx.x;
    int wy = win >> 5, wx = win & 31;
    extern __shared__ float sm[];
    float* xw  = sm;             // 4096
    float* ksm = xw + 4096;      // 4096  [h][px][d]
    float* qvs = ksm + 4096;     // 4160  (q; later v)
    float* wos = qvs + 4160;     // 4160  (v-conv weights; later out staging)
    float* rsm = wos + 4160;     // 900
    float* gsm = rsm + 900;      // 64
    int tid = threadIdx.x;
    const float* xb = x + ((size_t)cls * CN) * HWSZ;

    for (int id = tid; id < 512; id += 256) {
        int ch = id >> 3, i = id & 7;
        const float* p = xb + (size_t)ch * HWSZ + (wy * 8 + i) * HH + wx * 8;
        float4 a = *(const float4*)p;
        float4 b = *(const float4*)(p + 4);
        float* d = xw + ch * 64 + i * 8;
        d[0]=a.x; d[1]=a.y; d[2]=a.z; d[3]=a.w;
        d[4]=b.x; d[5]=b.y; d[6]=b.z; d[7]=b.w;
    }
    const float* gbase = g_qk + (size_t)(cls * NWIN + win) * 8192;
    for (int id = tid; id < 4096; id += 256)
        qvs[(id >> 6) * 65 + (id & 63)] = gbase[id];
    {
        const float4* gk4 = (const float4*)(gbase + 4096);
        float4* k4 = (float4*)ksm;
        for (int id = tid; id < 1024; id += 256) k4[id] = gk4[id];
    }
    const float* wvwb = wvw + (size_t)cls * 4096;
    for (int id = tid; id < 4096; id += 256)
        wos[(id >> 6) * 65 + (id & 63)] = wvwb[id];
    const float* rb = relb + cls * 900;
    for (int id = tid; id < 900; id += 256) rsm[id] = rb[id];
    if (tid < 64) {
        // inline good-mask: compare this class's mask vs max over classes
        float m[NCLS], mx = -1e30f;
        #pragma unroll
        for (int c = 0; c < NCLS; c++) {
            m[c] = g_mask[(c * NWIN + win) * 64 + tid];
            mx = fmaxf(mx, m[c]);
        }
        gsm[tid] = (m[cls] == mx) ? 1.f : -1.f;
    }
    __syncthreads();

    int h = tid >> 6, qp = tid & 63;
    int iq = qp >> 3, jq = qp & 7;
    u64 q2[8];
    #pragma unroll
    for (int j = 0; j < 8; j++)
        q2[j] = pk2(qvs[(h * 16 + 2 * j) * 65 + qp], qvs[(h * 16 + 2 * j + 1) * 65 + qp]);
    __syncthreads();

    // v conv into qvs as [h][px][d]
    {
        int ocp = tid >> 3;
        int px0 = (tid & 7) * 8;
        u64 acc[2][4];
        #pragma unroll
        for (int r = 0; r < 2; r++)
            #pragma unroll
            for (int j = 0; j < 4; j++) acc[r][j] = 0ull;
        const float* w0r = wos + (2 * ocp) * 65;
        const float* w1r = wos + (2 * ocp + 1) * 65;
        #pragma unroll 4
        for (int c = 0; c < 64; c++) {
            u64 wa = bc2(w0r[c]);
            u64 wb2 = bc2(w1r[c]);
            const ulonglong2* xp = (const ulonglong2*)(xw + c * 64 + px0);
            ulonglong2 x0 = xp[0], x1 = xp[1];
            fma2(acc[0][0], wa,  x0.x); fma2(acc[1][0], wb2, x0.x);
            fma2(acc[0][1], wa,  x0.y); fma2(acc[1][1], wb2, x0.y);
            fma2(acc[0][2], wa,  x1.x); fma2(acc[1][2], wb2, x1.x);
            fma2(acc[0][3], wa,  x1.y); fma2(acc[1][3], wb2, x1.y);
        }
        const float* vS = wvs + cls * 64;
        const float* vB = wvb + cls * 64;
        #pragma unroll
        for (int r = 0; r < 2; r++) {
            int oc = 2 * ocp + r;
            int hh2 = oc >> 4, d = oc & 15;
            float s = vS[oc], b = vB[oc];
            #pragma unroll
            for (int j = 0; j < 4; j++) {
                float2 v = upk(acc[r][j]);
                qvs[hh2 * 1024 + (px0 + 2 * j) * 16 + d]     = fmaxf(v.x * s + b, 0.f);
                qvs[hh2 * 1024 + (px0 + 2 * j + 1) * 16 + d] = fmaxf(v.y * s + b, 0.f);
            }
        }
    }
    __syncthreads();

    float mval = -1e30f, ssum = 0.f;
    u64 o2[8];
    #pragma unroll
    for (int j = 0; j < 8; j++) o2[j] = 0ull;
    const float* kb2 = ksm + h * 1024;
    const float* vb3 = qvs + h * 1024;
    #pragma unroll 4
    for (int kp = 0; kp < 64; kp++) {
        const ulonglong2* kr = (const ulonglong2*)(kb2 + kp * 16);
        ulonglong2 k0 = kr[0], k1 = kr[1], k2v = kr[2], k3 = kr[3];
        u64 d0 = 0ull, d1 = 0ull;
        fma2(d0, q2[0], k0.x);  fma2(d1, q2[1], k0.y);
        fma2(d0, q2[2], k1.x);  fma2(d1, q2[3], k1.y);
        fma2(d0, q2[4], k2v.x); fma2(d1, q2[5], k2v.y);
        fma2(d0, q2[6], k3.x);  fma2(d1, q2[7], k3.y);
        float2 a0 = upk(d0), a1 = upk(d1);
        int ridx = (iq - (kp >> 3) + 7) * 15 + (jq - (kp & 7) + 7);
        float aval = (a0.x + a0.y + a1.x + a1.y) * 0.25f + rsm[ridx * 4 + h];
        float mnew = fmaxf(mval, aval);
        float corr = __expf(mval - mnew);
        float p = __expf(aval - mnew);
        ssum = ssum * corr + p;
        mval = mnew;
        u64 c2 = bc2(corr), p2 = bc2(p * gsm[kp]);
        const ulonglong2* vr = (const ulonglong2*)(vb3 + kp * 16);
        ulonglong2 v0 = vr[0], v1 = vr[1], v2 = vr[2], v3 = vr[3];
        mul2(o2[0], c2); fma2(o2[0], p2, v0.x);
        mul2(o2[1], c2); fma2(o2[1], p2, v0.y);
        mul2(o2[2], c2); fma2(o2[2], p2, v1.x);
        mul2(o2[3], c2); fma2(o2[3], p2, v1.y);
        mul2(o2[4], c2); fma2(o2[4], p2, v2.x);
        mul2(o2[5], c2); fma2(o2[5], p2, v2.y);
        mul2(o2[6], c2); fma2(o2[6], p2, v3.x);
        mul2(o2[7], c2); fma2(o2[7], p2, v3.y);
    }
    u64 g2 = bc2(gsm[qp] / ssum);
    float* osm = wos;
    #pragma unroll
    for (int j = 0; j < 8; j++) {
        mul2(o2[j], g2);
        float2 ov = upk(o2[j]);
        int c0 = h * 16 + 2 * j;
        osm[c0 * 64 + qp]       = ov.x + xw[c0 * 64 + qp];
        osm[(c0 + 1) * 64 + qp] = ov.y + xw[(c0 + 1) * 64 + qp];
    }
    __syncthreads();

    float* ob = g_out1 + ((size_t)cls * CN) * HWSZ;
    for (int id = tid; id < 512; id += 256) {
        int ch = id >> 3, i = id & 7;
        const float* src = osm + ch * 64 + i * 8;
        float4 a4 = {src[0], src[1], src[2], src[3]};
        float4 b4 = {src[4], src[5], src[6], src[7]};
        float* p = ob + (size_t)ch * HWSZ + (wy * 8 + i) * HH + wx * 8;
        *(float4*)p = a4;
        *(float4*)(p + 4) = b4;
    }
}

// ---------------------------------------------------------------------------
// K4: sum of M conv3x3-BN-relu6 (R12/R8 exact). 8x4 tile, chunk=4, cp.async
// double-buffered transposed weights, LDS.128 tap loads.
// ---------------------------------------------------------------------------
template <int M, int OCC>
__global__ __launch_bounds__(256, OCC)
void k_conv3(int src_id, int dst_id,
             const float* __restrict__ s, const float* __restrict__ b, int m0) {
    int cls = blockIdx.z;
    int tx0 = blockIdx.x * 8, ty0 = blockIdx.y * 4;
    const float* src = (src_id == 0 ? g_out1 : g_x112) + (size_t)cls * CN * HWSZ;
    float* dst = (dst_id == 1 ? g_x112 : g_x223) + (size_t)cls * CN * HWSZ;
    extern __shared__ float sm[];
    float* ism = sm;                 // 4608
    float* wb0 = ism + 4608;         // M*2304
    float* wb1 = wb0 + M * 2304;     // M*2304
    unsigned smb = (unsigned)__cvta_generic_to_shared(sm);
    unsigned wbu[2] = { smb + 4608u * 4u, smb + (4608u + (unsigned)M * 2304u) * 4u };
    int tid = threadIdx.x;
    int oc = tid & 63, grp = tid >> 6;

    for (int id = tid; id < 4608; id += 256) {
        int c = id / 72, rem = id - c * 72;
        int r = rem / 12, p = rem - r * 12;
        int gy = ty0 + r - 1, gx = tx0 + (p >> 1) + 4 * (p & 1) - 1;
        float v = 0.f;
        if ((unsigned)gy < 256u && (unsigned)gx < 256u)
            v = src[(size_t)c * HWSZ + gy * HH + gx];
        ism[id] = v;
    }
    const float* wT = g_wT + (size_t)(cls * 6 + m0) * 576 * 64;

    for (int id = tid; id < M * 576; id += 256) {
        int mo = id / 576, i = id - mo * 576;
        cpasync16(wbu[0] + (unsigned)(mo * 2304 + i * 4) * 4u,
                  wT + mo * 36864 + i * 4);
    }
    cpcommit();

    u64 acc[M][4];
    #pragma unroll
    for (int m = 0; m < M; m++)
        #pragma unroll
        for (int j = 0; j < 4; j++) acc[m][j] = 0ull;

    for (int ci = 0; ci < 16; ci++) {
        cpwait0();
        __syncthreads();
        const float* cur = (ci & 1) ? wb1 : wb0;
        if (ci < 15) {
            unsigned dstb = wbu[(ci + 1) & 1];
            const float* srcb = wT + (ci + 1) * 2304;
            for (int id = tid; id < M * 576; id += 256) {
                int mo = id / 576, i = id - mo * 576;
                cpasync16(dstb + (unsigned)(mo * 2304 + i * 4) * 4u,
                          srcb + mo * 36864 + i * 4);
            }
        }
        cpcommit();
        #pragma unroll
        for (int lc = 0; lc < 4; lc++) {
            const float* ib = ism + (ci * 4 + lc) * 72 + grp * 12;
            #pragma unroll
            for (int ky = 0; ky < 3; ky++) {
                const ulonglong2* P = (const ulonglong2*)(ib + ky * 12);
                ulonglong2 pa = P[0], pb = P[1], pc = P[2];
                u64 p0 = pa.x, p1 = pa.y, p2 = pb.x, p3 = pb.y, p4 = pc.x, p5 = pc.y;
                #pragma unroll
                for (int m = 0; m < M; m++) {
                    const float* wp = cur + m * 2304 + (lc * 9 + ky * 3) * 64 + oc;
                    u64 w0 = bc2(wp[0]), w1 = bc2(wp[64]), w2 = bc2(wp[128]);
                    fma2(acc[m][0], w0, p0); fma2(acc[m][0], w1, p1); fma2(acc[m][0], w2, p2);
                    fma2(acc[m][1], w0, p1); fma2(acc[m][1], w1, p2); fma2(acc[m][1], w2, p3);
                    fma2(acc[m][2], w0, p2); fma2(acc[m][2], w1, p3); fma2(acc[m][2], w2, p4);
                    fma2(acc[m][3], w0, p3); fma2(acc[m][3], w1, p4); fma2(acc[m][3], w2, p5);
                }
            }
        }
    }

    float res[8];
    #pragma unroll
    for (int j = 0; j < 8; j++) res[j] = 0.f;
    #pragma unroll
    for (int m = 0; m < M; m++) {
        float sv = s[((size_t)cls * 6 + m0 + m) * 64 + oc];
        float bv = b[((size_t)cls * 6 + m0 + m) * 64 + oc];
        #pragma unroll
        for (int j = 0; j < 4; j++) {
            float2 v = upk(acc[m][j]);
            res[j]     += fminf(fmaxf(v.x * sv + bv, 0.f), 6.f);
            res[j + 4] += fminf(fmaxf(v.y * sv + bv, 0.f), 6.f);
        }
    }
    float* osm = wb0;
    {
        float4 a4 = {res[0], res[1], res[2], res[3]};
        float4 b4 = {res[4], res[5], res[6], res[7]};
        *(float4*)(osm + oc * 36 + grp * 8)     = a4;
        *(float4*)(osm + oc * 36 + grp * 8 + 4) = b4;
    }
    __syncthreads();
    for (int id = tid; id < 512; id += 256) {
        int oc2 = id >> 3, rq = id & 7, r = rq >> 1, q = rq & 1;
        float4 v = *(const float4*)(osm + oc2 * 36 + r * 8 + q * 4);
        *(float4*)(dst + (size_t)oc2 * HWSZ + (ty0 + r) * HH + tx0 + q * 4) = v;
    }
}

// ---------------------------------------------------------------------------
// K5 (fused, R12 exact): x33 conv3x3 in-block + concat 1x1-BN + residual.
// ---------------------------------------------------------------------------
__global__ __launch_bounds__(256, 3)
void k_outf(const float* __restrict__ s, const float* __restrict__ b,
            const float* __restrict__ catw, const float* __restrict__ cats,
            const float* __restrict__ catb, float* __restrict__ out) {
    int cls = blockIdx.z;
    int tx0 = blockIdx.x * 16, ty0 = blockIdx.y * 4;
    size_t cbase = (size_t)cls * CN * HWSZ;
    const float* x223 = g_x223 + cbase;
    const float* x112 = g_x112 + cbase;
    extern __shared__ float sm[];
    float* ism  = sm;            // 7680
    float* wbuf = ism + 7680;    // 2304
    float* x1sm = wbuf + 2304;   // 4096
    float* x3sm = x1sm + 4096;   // 4224
    unsigned smb = (unsigned)__cvta_generic_to_shared(sm);
    unsigned wbu[2] = { smb + 7680u * 4u, smb + (7680u + 1152u) * 4u };
    int tid = threadIdx.x;
    int oc = tid & 63, grp = tid >> 6;
    const float* wT = g_wT + (size_t)(cls * 6 + 5) * 576 * 64;

    for (int id = tid; id < 288; id += 256)
        cpasync16(wbu[0] + (unsigned)id * 16u, wT + id * 4);
    cpcommit();

    for (int id = tid; id < 7680; id += 256) {
        int c = id / 120, rem = id - c * 120;
        int r = rem / 20, p = rem - r * 20;
        int gy = ty0 + r - 1, gx = tx0 + (p >> 1) + 8 * (p & 1) - 1;
        float v = 0.f;
        if ((unsigned)gy < 256u && (unsigned)gx < 256u)
            v = x223[(size_t)c * HWSZ + gy * HH + gx];
        ism[id] = v;
    }
    for (int id = tid; id < 4096; id += 256) {
        int c = id >> 6, px = id & 63, row = px >> 4, pp = px & 15;
        int col = (pp >> 1) + 8 * (pp & 1);
        x1sm[id] = x112[(size_t)c * HWSZ + (ty0 + row) * HH + tx0 + col];
    }

    u64 acc[8];
    #pragma unroll
    for (int j = 0; j < 8; j++) acc[j] = 0ull;
    for (int ci = 0; ci < 32; ci++) {
        cpwait0();
        __syncthreads();
        const float* cur = wbuf + (ci & 1) * 1152;
        if (ci < 31) {
            unsigned dstb = wbu[(ci + 1) & 1];
            const float* srcb = wT + (ci + 1) * 1152;
            for (int id = tid; id < 288; id += 256)
                cpasync16(dstb + (unsigned)id * 16u, srcb + id * 4);
        }
        cpcommit();
        #pragma unroll
        for (int c = 0; c < 2; c++) {
            const float* ib = ism + (ci * 2 + c) * 120 + grp * 20;
            #pragma unroll
            for (int ky = 0; ky < 3; ky++) {
                const ulonglong2* P = (const ulonglong2*)(ib + ky * 20);
                ulonglong2 pa = P[0], pb = P[1], pc = P[2], pd = P[3], pe = P[4];
                u64 p[10] = {pa.x, pa.y, pb.x, pb.y, pc.x, pc.y, pd.x, pd.y, pe.x, pe.y};
                const float* wp = cur + (c * 9 + ky * 3) * 64 + oc;
                u64 w0 = bc2(wp[0]), w1 = bc2(wp[64]), w2 = bc2(wp[128]);
                #pragma unroll
                for (int j = 0; j < 8; j++) {
                    fma2(acc[j], w0, p[j]);
                    fma2(acc[j], w1, p[j + 1]);
                    fma2(acc[j], w2, p[j + 2]);
                }
            }
        }
    }
    {
        float sv = s[((size_t)cls * 6 + 5) * 64 + oc];
        float bv = b[((size_t)cls * 6 + 5) * 64 + oc];
        #pragma unroll
        for (int j = 0; j < 8; j++) {
            float2 v = upk(acc[j]);
            x3sm[oc * 66 + grp * 16 + 2 * j]     = fminf(fmaxf(v.x * sv + bv, 0.f), 6.f);
            x3sm[oc * 66 + grp * 16 + 2 * j + 1] = fminf(fmaxf(v.y * sv + bv, 0.f), 6.f);
        }
    }

    int ocp = tid >> 3, seg = tid & 7;
    int row = seg >> 1, pj0 = (seg & 1) * 4;
    u64 y[2][4];
    #pragma unroll
    for (int r = 0; r < 2; r++)
        #pragma unroll
        for (int k = 0; k < 4; k++) y[r][k] = 0ull;
    const float* cwb = catw + (size_t)cls * 64 * 192;

    #pragma unroll
    for (int sidx = 0; sidx < 3; sidx++) {
        #pragma unroll
        for (int half = 0; half < 2; half++) {
            __syncthreads();
            for (int id = tid; id < 2048; id += 256) {
                int o2 = id >> 5, c = id & 31;
                wbuf[o2 * 33 + c] = cwb[o2 * 192 + sidx * 64 + half * 32 + c];
            }
            __syncthreads();
            const float* w0r = wbuf + (2 * ocp) * 33;
            const float* w1r = wbuf + (2 * ocp + 1) * 33;
            #pragma unroll 4
            for (int c = 0; c < 32; c++) {
                int cg = half * 32 + c;
                u64 wa = bc2(w0r[c]);
                u64 wb2 = bc2(w1r[c]);
                const u64* xp;
                if (sidx == 0)      xp = (const u64*)(x1sm + cg * 64 + row * 16 + 2 * pj0);
                else if (sidx == 1) xp = (const u64*)(ism + cg * 120 + (row + 1) * 20 + 2 * (pj0 + 1));
                else                xp = (const u64*)(x3sm + cg * 66 + row * 16 + 2 * pj0);
                #pragma unroll
                for (int k = 0; k < 4; k++) {
                    u64 v = xp[k];
                    fma2(y[0][k], wa,  v);
                    fma2(y[1][k], wb2, v);
                }
            }
        }
    }

    const float* o1 = g_out1 + cbase;
    float* ob = out + ((size_t)cls * CN) * HWSZ;
    #pragma unroll
    for (int rr = 0; rr < 2; rr++) {
        int o2 = 2 * ocp + rr;
        float csv = cats[cls * 64 + o2], cbv = catb[cls * 64 + o2];
        float lo[4], hi[4];
        #pragma unroll
        for (int k = 0; k < 4; k++) {
            float2 t = upk(y[rr][k]);
            lo[k] = t.x * csv + cbv;
            hi[k] = t.y * csv + cbv;
        }
        const float* rp = o1 + (size_t)o2 * HWSZ + (ty0 + row) * HH + tx0 + pj0;
        float4 ra = *(const float4*)rp;
        float4 rb = *(const float4*)(rp + 8);
        float4 oa, obv;
        oa.x = fmaxf(lo[0] + ra.x, 0.f);
        oa.y = fmaxf(lo[1] + ra.y, 0.f);
        oa.z = fmaxf(lo[2] + ra.z, 0.f);
        oa.w = fmaxf(lo[3] + ra.w, 0.f);
        obv.x = fmaxf(hi[0] + rb.x, 0.f);
        obv.y = fmaxf(hi[1] + rb.y, 0.f);
        obv.z = fmaxf(hi[2] + rb.z, 0.f);
        obv.w = fmaxf(hi[3] + rb.w, 0.f);
        float* op = ob + (size_t)o2 * HWSZ + (ty0 + row) * HH + tx0 + pj0;
        *(float4*)op = oa;
        *(float4*)(op + 8) = obv;
    }
}

// ---------------------------------------------------------------------------
extern "C" void kernel_launch(void* const* d_in, const int* in_sizes, int n_in,
                              void* d_out, int out_size) {
    const float* x    = (const float*)d_in[0];
    const float* qkw  = (const float*)d_in[1];
    const float* qks  = (const float*)d_in[2];
    const float* qkb  = (const float*)d_in[3];
    const float* relb = (const float*)d_in[4];
    const float* wvw  = (const float*)d_in[5];
    const float* wvs  = (const float*)d_in[6];
    const float* wvb  = (const float*)d_in[7];
    const float* mmsw = (const float*)d_in[8];
    const float* mmss = (const float*)d_in[9];
    const float* mmsb = (const float*)d_in[10];
    const float* catw = (const float*)d_in[11];
    const float* cats = (const float*)d_in[12];
    const float* catb = (const float*)d_in[13];
    float* out = (float*)d_out;

    const int SM_MASK = (4096 + 4160 + 8320 + 64 + 900) * 4;          // 70160
    const int SM_ATTN = (4096 + 4096 + 4160 + 4160 + 900 + 64) * 4;   // 69904
    const int SM_C3   = (4608 + 2 * 3 * 2304) * 4;                    // 73728
    const int SM_C2   = (4608 + 2 * 2 * 2304) * 4;                    // 55296
    const int SM_OUTF = (7680 + 2304 + 4096 + 4224) * 4;              // 73216

    cudaFuncSetAttribute(k_mask, cudaFuncAttributeMaxDynamicSharedMemorySize, SM_MASK);
    cudaFuncSetAttribute(k_attn, cudaFuncAttributeMaxDynamicSharedMemorySize, SM_ATTN);
    cudaFuncSetAttribute((const void*)k_conv3<3,3>, cudaFuncAttributeMaxDynamicSharedMemorySize, SM_C3);
    cudaFuncSetAttribute((const void*)k_conv3<2,4>, cudaFuncAttributeMaxDynamicSharedMemorySize, SM_C2);
    cudaFuncSetAttribute(k_outf, cudaFuncAttributeMaxDynamicSharedMemorySize, SM_OUTF);

    k_prep<<<(NCLS * 6 * 64 * 576 + 255) / 256, 256>>>(mmsw);
    k_mask<<<dim3(NWIN, NCLS), 256, SM_MASK>>>(x, qkw, qks, qkb, relb);
    k_attn<<<dim3(NWIN, NCLS), 256, SM_ATTN>>>(x, relb, wvw, wvs, wvb);
    dim3 cg(32, 64, NCLS);
    k_conv3<3,3><<<cg, 256, SM_C3>>>(0, 1, mmss, mmsb, 0);
    k_conv3<2,4><<<cg, 256, SM_C2>>>(1, 2, mmss, mmsb, 3);
    dim3 og(16, 64, NCLS);
    k_outf<<<og, 256, SM_OUTF>>>(mmss, mmsb, catw, cats, catb, out);
}

// round 17
// speedup vs baseline: 1.0183x; 1.0183x over previous
#include <cuda_runtime.h>

#define CN    64
#define HH    256
#define HWSZ  65536
#define NCLS  6
#define NWIN  1024

typedef unsigned long long u64;

__device__ __forceinline__ u64 pk2(float lo, float hi) {
    u64 r; asm("mov.b64 %0, {%1, %2};" : "=l"(r) : "f"(lo), "f"(hi)); return r;
}
__device__ __forceinline__ u64 bc2(float v) { return pk2(v, v); }
__device__ __forceinline__ void fma2(u64& a, u64 x, u64 y) {
    asm("fma.rn.f32x2 %0, %1, %2, %0;" : "+l"(a) : "l"(x), "l"(y));
}
__device__ __forceinline__ void mul2(u64& a, u64 x) {
    asm("mul.rn.f32x2 %0, %0, %1;" : "+l"(a) : "l"(x));
}
__device__ __forceinline__ float2 upk(u64 v) {
    float2 r; asm("mov.b64 {%0, %1}, %2;" : "=f"(r.x), "=f"(r.y) : "l"(v)); return r;
}
__device__ __forceinline__ void cpasync16(unsigned dst, const void* src) {
    asm volatile("cp.async.cg.shared.global [%0], [%1], 16;" :: "r"(dst), "l"(src));
}
__device__ __forceinline__ void cpcommit() {
    asm volatile("cp.async.commit_group;");
}
__device__ __forceinline__ void cpwait0() {
    asm volatile("cp.async.wait_group 0;" ::: "memory");
}

// ---------------- scratch (device globals; no allocations allowed) ----------
__device__ float g_mask[NCLS * NWIN * 64];
__device__ float g_qk[(size_t)NCLS * NWIN * 8192];    // per-window q (4096) + k (4096)
__device__ float g_wT[NCLS * 6 * 576 * 64];           // transposed conv weights [cm][tap][oc]
__device__ float g_out1[(size_t)NCLS * CN * HWSZ];    // x + class_attn
__device__ float g_x112[(size_t)NCLS * CN * HWSZ];
__device__ float g_x223[(size_t)NCLS * CN * HWSZ];

// ---------------------------------------------------------------------------
// K0: transpose conv weights -> [cls*6+m][tap(ic*9+ky*3+kx)][oc]
// ---------------------------------------------------------------------------
__global__ void k_prep(const float* __restrict__ w) {
    int id = blockIdx.x * 256 + threadIdx.x;
    if (id >= NCLS * 6 * 64 * 576) return;
    int cm = id / (64 * 576);
    int rem = id - cm * 64 * 576;
    int oc = rem / 576, tap = rem - oc * 576;
    g_wT[(cm * 576 + tap) * 64 + oc] = w[id];
}

// ---------------------------------------------------------------------------
// K1: qk conv in two 64-oc phases (R12 exact).
// ---------------------------------------------------------------------------
__global__ __launch_bounds__(256, 3)
void k_mask(const float* __restrict__ x, const float* __restrict__ qkw,
            const float* __restrict__ qks, const float* __restrict__ qkb,
            const float* __restrict__ relb) {
    int cls = blockIdx.y, win = blockIdx.x;
    int wy = win >> 5, wx = win & 31;
    extern __shared__ float sm[];
    float* xw   = sm;            // 4096
    float* wsm  = xw + 4096;     // 4160 (reused per phase)
    float* qk   = wsm + 4160;    // 8320
    float* qsum = qk + 8320;     // 64
    float* rsm  = qsum + 64;     // 900
    int tid = threadIdx.x;
    const float* xb = x + ((size_t)cls * CN) * HWSZ;

    for (int id = tid; id < 512; id += 256) {
        int ch = id >> 3, i = id & 7;
        const float* p = xb + (size_t)ch * HWSZ + (wy * 8 + i) * HH + wx * 8;
        float4 a = *(const float4*)p;
        float4 b = *(const float4*)(p + 4);
        float* d = xw + ch * 64 + i * 8;
        d[0]=a.x; d[1]=a.y; d[2]=a.z; d[3]=a.w;
        d[4]=b.x; d[5]=b.y; d[6]=b.z; d[7]=b.w;
    }
    const float* rb = relb + cls * 900;
    for (int id = tid; id < 900; id += 256) rsm[id] = rb[id];

    const float* sS = qks + cls * 128;
    const float* sB = qkb + cls * 128;
    int ocp = tid >> 3;
    int px0 = (tid & 7) * 8;

    #pragma unroll
    for (int ph = 0; ph < 2; ph++) {
        __syncthreads();
        const float* wb = qkw + (size_t)cls * 8192 + ph * 4096;
        for (int id = tid; id < 4096; id += 256)
            wsm[(id >> 6) * 65 + (id & 63)] = wb[id];
        __syncthreads();

        u64 acc[2][4];
        #pragma unroll
        for (int r = 0; r < 2; r++)
            #pragma unroll
            for (int j = 0; j < 4; j++) acc[r][j] = 0ull;
        const float* w0r = wsm + (2 * ocp) * 65;
        const float* w1r = wsm + (2 * ocp + 1) * 65;
        #pragma unroll 4
        for (int c = 0; c < 64; c++) {
            u64 wa = bc2(w0r[c]);
            u64 wb2 = bc2(w1r[c]);
            const ulonglong2* xp = (const ulonglong2*)(xw + c * 64 + px0);
            ulonglong2 x0 = xp[0], x1 = xp[1];
            fma2(acc[0][0], wa,  x0.x); fma2(acc[1][0], wb2, x0.x);
            fma2(acc[0][1], wa,  x0.y); fma2(acc[1][1], wb2, x0.y);
            fma2(acc[0][2], wa,  x1.x); fma2(acc[1][2], wb2, x1.x);
            fma2(acc[0][3], wa,  x1.y); fma2(acc[1][3], wb2, x1.y);
        }
        #pragma unroll
        for (int r = 0; r < 2; r++) {
            int ocl = 2 * ocp + r;
            int oc = ph * 64 + ocl;
            float s = sS[oc], b = sB[oc];
            #pragma unroll
            for (int j = 0; j < 4; j++) {
                float2 v = upk(acc[r][j]);
                qk[oc * 65 + px0 + 2 * j]     = fmaxf(v.x * s + b, 0.f);
                qk[oc * 65 + px0 + 2 * j + 1] = fmaxf(v.y * s + b, 0.f);
            }
        }
    }
    __syncthreads();

    float* gbase = g_qk + (size_t)(cls * NWIN + win) * 8192;
    for (int id = tid; id < 4096; id += 256)
        gbase[id] = qk[(id >> 6) * 65 + (id & 63)];
    for (int id = tid; id < 4096; id += 256) {
        int h = id >> 10, rem = id & 1023, px = rem >> 4, d = rem & 15;
        gbase[4096 + id] = qk[(64 + h * 16 + d) * 65 + px];
    }
    if (tid < 64) {
        float s = 0.f;
        const float* r = qk + tid * 65;
        #pragma unroll 16
        for (int p = 0; p < 64; p++) s += r[p];
        qsum[tid] = s;
    }
    __syncthreads();

    if (tid < 64) {
        int kp = tid, ik = kp >> 3, jk = kp & 7;
        float dot = 0.f;
        #pragma unroll 16
        for (int ch = 0; ch < 64; ch++) dot += qsum[ch] * qk[(64 + ch) * 65 + kp];
        float rbv = 0.f;
        for (int q = 0; q < 64; q++) {
            int ridx = ((q >> 3) - ik + 7) * 15 + ((q & 7) - jk + 7);
            const float* r4 = rsm + ridx * 4;
            rbv += r4[0] + r4[1] + r4[2] + r4[3];
        }
        g_mask[(cls * NWIN + win) * 64 + kp] = dot * (0.25f / 256.f) + rbv * (1.f / 256.f);
    }
}

// ---------------------------------------------------------------------------
// K3: attention, online-softmax single pass, inline good-mask (R16 exact).
// ---------------------------------------------------------------------------
__global__ __launch_bounds__(256, 3)
void k_attn(const float* __restrict__ x, const float* __restrict__ relb,
            const float* __restrict__ wvw, const float* __restrict__ wvs,
            const float* __restrict__ wvb) {
    int cls = blockIdx.y, win = blockIdx.x;
    int wy = win >> 5, wx = win & 31;
    extern __shared__ float sm[];
    float* xw  = sm;             // 4096
    float* ksm = xw + 4096;      // 4096  [h][px][d]
    float* qvs = ksm + 4096;     // 4160  (q; later v)
    float* wos = qvs + 4160;     // 4160  (v-conv weights; later out staging)
    float* rsm = wos + 4160;     // 900
    float* gsm = rsm + 900;      // 64
    int tid = threadIdx.x;
    const float* xb = x + ((size_t)cls * CN) * HWSZ;

    for (int id = tid; id < 512; id += 256) {
        int ch = id >> 3, i = id & 7;
        const float* p = xb + (size_t)ch * HWSZ + (wy * 8 + i) * HH + wx * 8;
        float4 a = *(const float4*)p;
        float4 b = *(const float4*)(p + 4);
        float* d = xw + ch * 64 + i * 8;
        d[0]=a.x; d[1]=a.y; d[2]=a.z; d[3]=a.w;
        d[4]=b.x; d[5]=b.y; d[6]=b.z; d[7]=b.w;
    }
    const float* gbase = g_qk + (size_t)(cls * NWIN + win) * 8192;
    for (int id = tid; id < 4096; id += 256)
        qvs[(id >> 6) * 65 + (id & 63)] = gbase[id];
    {
        const float4* gk4 = (const float4*)(gbase + 4096);
        float4* k4 = (float4*)ksm;
        for (int id = tid; id < 1024; id += 256) k4[id] = gk4[id];
    }
    const float* wvwb = wvw + (size_t)cls * 4096;
    for (int id = tid; id < 4096; id += 256)
        wos[(id >> 6) * 65 + (id & 63)] = wvwb[id];
    const float* rb = relb + cls * 900;
    for (int id = tid; id < 900; id += 256) rsm[id] = rb[id];
    if (tid < 64) {
        float m[NCLS], mx = -1e30f;
        #pragma unroll
        for (int c = 0; c < NCLS; c++) {
            m[c] = g_mask[(c * NWIN + win) * 64 + tid];
            mx = fmaxf(mx, m[c]);
        }
        gsm[tid] = (m[cls] == mx) ? 1.f : -1.f;
    }
    __syncthreads();

    int h = tid >> 6, qp = tid & 63;
    int iq = qp >> 3, jq = qp & 7;
    u64 q2[8];
    #pragma unroll
    for (int j = 0; j < 8; j++)
        q2[j] = pk2(qvs[(h * 16 + 2 * j) * 65 + qp], qvs[(h * 16 + 2 * j + 1) * 65 + qp]);
    __syncthreads();

    {
        int ocp = tid >> 3;
        int px0 = (tid & 7) * 8;
        u64 acc[2][4];
        #pragma unroll
        for (int r = 0; r < 2; r++)
            #pragma unroll
            for (int j = 0; j < 4; j++) acc[r][j] = 0ull;
        const float* w0r = wos + (2 * ocp) * 65;
        const float* w1r = wos + (2 * ocp + 1) * 65;
        #pragma unroll 4
        for (int c = 0; c < 64; c++) {
            u64 wa = bc2(w0r[c]);
            u64 wb2 = bc2(w1r[c]);
            const ulonglong2* xp = (const ulonglong2*)(xw + c * 64 + px0);
            ulonglong2 x0 = xp[0], x1 = xp[1];
            fma2(acc[0][0], wa,  x0.x); fma2(acc[1][0], wb2, x0.x);
            fma2(acc[0][1], wa,  x0.y); fma2(acc[1][1], wb2, x0.y);
            fma2(acc[0][2], wa,  x1.x); fma2(acc[1][2], wb2, x1.x);
            fma2(acc[0][3], wa,  x1.y); fma2(acc[1][3], wb2, x1.y);
        }
        const float* vS = wvs + cls * 64;
        const float* vB = wvb + cls * 64;
        #pragma unroll
        for (int r = 0; r < 2; r++) {
            int oc = 2 * ocp + r;
            int hh2 = oc >> 4, d = oc & 15;
            float s = vS[oc], b = vB[oc];
            #pragma unroll
            for (int j = 0; j < 4; j++) {
                float2 v = upk(acc[r][j]);
                qvs[hh2 * 1024 + (px0 + 2 * j) * 16 + d]     = fmaxf(v.x * s + b, 0.f);
                qvs[hh2 * 1024 + (px0 + 2 * j + 1) * 16 + d] = fmaxf(v.y * s + b, 0.f);
            }
        }
    }
    __syncthreads();

    float mval = -1e30f, ssum = 0.f;
    u64 o2[8];
    #pragma unroll
    for (int j = 0; j < 8; j++) o2[j] = 0ull;
    const float* kb2 = ksm + h * 1024;
    const float* vb3 = qvs + h * 1024;
    #pragma unroll 4
    for (int kp = 0; kp < 64; kp++) {
        const ulonglong2* kr = (const ulonglong2*)(kb2 + kp * 16);
        ulonglong2 k0 = kr[0], k1 = kr[1], k2v = kr[2], k3 = kr[3];
        u64 d0 = 0ull, d1 = 0ull;
        fma2(d0, q2[0], k0.x);  fma2(d1, q2[1], k0.y);
        fma2(d0, q2[2], k1.x);  fma2(d1, q2[3], k1.y);
        fma2(d0, q2[4], k2v.x); fma2(d1, q2[5], k2v.y);
        fma2(d0, q2[6], k3.x);  fma2(d1, q2[7], k3.y);
        float2 a0 = upk(d0), a1 = upk(d1);
        int ridx = (iq - (kp >> 3) + 7) * 15 + (jq - (kp & 7) + 7);
        float aval = (a0.x + a0.y + a1.x + a1.y) * 0.25f + rsm[ridx * 4 + h];
        float mnew = fmaxf(mval, aval);
        float corr = __expf(mval - mnew);
        float p = __expf(aval - mnew);
        ssum = ssum * corr + p;
        mval = mnew;
        u64 c2 = bc2(corr), p2 = bc2(p * gsm[kp]);
        const ulonglong2* vr = (const ulonglong2*)(vb3 + kp * 16);
        ulonglong2 v0 = vr[0], v1 = vr[1], v2 = vr[2], v3 = vr[3];
        mul2(o2[0], c2); fma2(o2[0], p2, v0.x);
        mul2(o2[1], c2); fma2(o2[1], p2, v0.y);
        mul2(o2[2], c2); fma2(o2[2], p2, v1.x);
        mul2(o2[3], c2); fma2(o2[3], p2, v1.y);
        mul2(o2[4], c2); fma2(o2[4], p2, v2.x);
        mul2(o2[5], c2); fma2(o2[5], p2, v2.y);
        mul2(o2[6], c2); fma2(o2[6], p2, v3.x);
        mul2(o2[7], c2); fma2(o2[7], p2, v3.y);
    }
    u64 g2 = bc2(gsm[qp] / ssum);
    float* osm = wos;
    #pragma unroll
    for (int j = 0; j < 8; j++) {
        mul2(o2[j], g2);
        float2 ov = upk(o2[j]);
        int c0 = h * 16 + 2 * j;
        osm[c0 * 64 + qp]       = ov.x + xw[c0 * 64 + qp];
        osm[(c0 + 1) * 64 + qp] = ov.y + xw[(c0 + 1) * 64 + qp];
    }
    __syncthreads();

    float* ob = g_out1 + ((size_t)cls * CN) * HWSZ;
    for (int id = tid; id < 512; id += 256) {
        int ch = id >> 3, i = id & 7;
        const float* src = osm + ch * 64 + i * 8;
        float4 a4 = {src[0], src[1], src[2], src[3]};
        float4 b4 = {src[4], src[5], src[6], src[7]};
        float* p = ob + (size_t)ch * HWSZ + (wy * 8 + i) * HH + wx * 8;
        *(float4*)p = a4;
        *(float4*)(p + 4) = b4;
    }
}

// ---------------------------------------------------------------------------
// K4a: 3-branch conv3x3-BN-relu6 sum (R12 exact). 8x4 tile, chunk=4.
// ---------------------------------------------------------------------------
template <int M, int OCC>
__global__ __launch_bounds__(256, OCC)
void k_conv3(int src_id, int dst_id,
             const float* __restrict__ s, const float* __restrict__ b, int m0) {
    int cls = blockIdx.z;
    int tx0 = blockIdx.x * 8, ty0 = blockIdx.y * 4;
    const float* src = (src_id == 0 ? g_out1 : g_x112) + (size_t)cls * CN * HWSZ;
    float* dst = (dst_id == 1 ? g_x112 : g_x223) + (size_t)cls * CN * HWSZ;
    extern __shared__ float sm[];
    float* ism = sm;                 // 4608
    float* wb0 = ism + 4608;         // M*2304
    float* wb1 = wb0 + M * 2304;     // M*2304
    unsigned smb = (unsigned)__cvta_generic_to_shared(sm);
    unsigned wbu[2] = { smb + 4608u * 4u, smb + (4608u + (unsigned)M * 2304u) * 4u };
    int tid = threadIdx.x;
    int oc = tid & 63, grp = tid >> 6;

    for (int id = tid; id < 4608; id += 256) {
        int c = id / 72, rem = id - c * 72;
        int r = rem / 12, p = rem - r * 12;
        int gy = ty0 + r - 1, gx = tx0 + (p >> 1) + 4 * (p & 1) - 1;
        float v = 0.f;
        if ((unsigned)gy < 256u && (unsigned)gx < 256u)
            v = src[(size_t)c * HWSZ + gy * HH + gx];
        ism[id] = v;
    }
    const float* wT = g_wT + (size_t)(cls * 6 + m0) * 576 * 64;

    for (int id = tid; id < M * 576; id += 256) {
        int mo = id / 576, i = id - mo * 576;
        cpasync16(wbu[0] + (unsigned)(mo * 2304 + i * 4) * 4u,
                  wT + mo * 36864 + i * 4);
    }
    cpcommit();

    u64 acc[M][4];
    #pragma unroll
    for (int m = 0; m < M; m++)
        #pragma unroll
        for (int j = 0; j < 4; j++) acc[m][j] = 0ull;

    for (int ci = 0; ci < 16; ci++) {
        cpwait0();
        __syncthreads();
        const float* cur = (ci & 1) ? wb1 : wb0;
        if (ci < 15) {
            unsigned dstb = wbu[(ci + 1) & 1];
            const float* srcb = wT + (ci + 1) * 2304;
            for (int id = tid; id < M * 576; id += 256) {
                int mo = id / 576, i = id - mo * 576;
                cpasync16(dstb + (unsigned)(mo * 2304 + i * 4) * 4u,
                          srcb + mo * 36864 + i * 4);
            }
        }
        cpcommit();
        #pragma unroll
        for (int lc = 0; lc < 4; lc++) {
            const float* ib = ism + (ci * 4 + lc) * 72 + grp * 12;
            #pragma unroll
            for (int ky = 0; ky < 3; ky++) {
                const ulonglong2* P = (const ulonglong2*)(ib + ky * 12);
                ulonglong2 pa = P[0], pb = P[1], pc = P[2];
                u64 p0 = pa.x, p1 = pa.y, p2 = pb.x, p3 = pb.y, p4 = pc.x, p5 = pc.y;
                #pragma unroll
                for (int m = 0; m < M; m++) {
                    const float* wp = cur + m * 2304 + (lc * 9 + ky * 3) * 64 + oc;
                    u64 w0 = bc2(wp[0]), w1 = bc2(wp[64]), w2 = bc2(wp[128]);
                    fma2(acc[m][0], w0, p0); fma2(acc[m][0], w1, p1); fma2(acc[m][0], w2, p2);
                    fma2(acc[m][1], w0, p1); fma2(acc[m][1], w1, p2); fma2(acc[m][1], w2, p3);
                    fma2(acc[m][2], w0, p2); fma2(acc[m][2], w1, p3); fma2(acc[m][2], w2, p4);
                    fma2(acc[m][3], w0, p3); fma2(acc[m][3], w1, p4); fma2(acc[m][3], w2, p5);
                }
            }
        }
    }

    float res[8];
    #pragma unroll
    for (int j = 0; j < 8; j++) res[j] = 0.f;
    #pragma unroll
    for (int m = 0; m < M; m++) {
        float sv = s[((size_t)cls * 6 + m0 + m) * 64 + oc];
        float bv = b[((size_t)cls * 6 + m0 + m) * 64 + oc];
        #pragma unroll
        for (int j = 0; j < 4; j++) {
            float2 v = upk(acc[m][j]);
            res[j]     += fminf(fmaxf(v.x * sv + bv, 0.f), 6.f);
            res[j + 4] += fminf(fmaxf(v.y * sv + bv, 0.f), 6.f);
        }
    }
    float* osm = wb0;
    {
        float4 a4 = {res[0], res[1], res[2], res[3]};
        float4 b4 = {res[4], res[5], res[6], res[7]};
        *(float4*)(osm + oc * 36 + grp * 8)     = a4;
        *(float4*)(osm + oc * 36 + grp * 8 + 4) = b4;
    }
    __syncthreads();
    for (int id = tid; id < 512; id += 256) {
        int oc2 = id >> 3, rq = id & 7, r = rq >> 1, q = rq & 1;
        float4 v = *(const float4*)(osm + oc2 * 36 + r * 8 + q * 4);
        *(float4*)(dst + (size_t)oc2 * HWSZ + (ty0 + r) * HH + tx0 + q * 4) = v;
    }
}

// ---------------------------------------------------------------------------
// K4b: 2-branch conv3x3 sum, 16x4 tile, interleaved (px, px+8) pairs,
// chunk=4 plain weights double-buffered. Higher FMA density: each bc2 feeds
// 8 fma2; blocks halve vs the 8-wide version.
// ---------------------------------------------------------------------------
__global__ __launch_bounds__(256, 3)
void k_conv3w(const float* __restrict__ s, const float* __restrict__ b) {
    int cls = blockIdx.z;
    int tx0 = blockIdx.x * 16, ty0 = blockIdx.y * 4;
    const float* src = g_x112 + (size_t)cls * CN * HWSZ;
    float* dst = g_x223 + (size_t)cls * CN * HWSZ;
    extern __shared__ float sm[];
    float* ism = sm;                 // 64*6*20 = 7680 (interleaved halo)
    float* wb0 = ism + 7680;         // 2*2304
    float* wb1 = wb0 + 2 * 2304;     // 2*2304
    unsigned smb = (unsigned)__cvta_generic_to_shared(sm);
    unsigned wbu[2] = { smb + 7680u * 4u, smb + (7680u + 4608u) * 4u };
    int tid = threadIdx.x;
    int oc = tid & 63, grp = tid >> 6;

    // interleaved halo: slot p -> col (p>>1)+8*(p&1)-1
    for (int id = tid; id < 7680; id += 256) {
        int c = id / 120, rem = id - c * 120;
        int r = rem / 20, p = rem - r * 20;
        int gy = ty0 + r - 1, gx = tx0 + (p >> 1) + 8 * (p & 1) - 1;
        float v = 0.f;
        if ((unsigned)gy < 256u && (unsigned)gx < 256u)
            v = src[(size_t)c * HWSZ + gy * HH + gx];
        ism[id] = v;
    }
    const float* wT = g_wT + (size_t)(cls * 6 + 3) * 576 * 64;

    for (int id = tid; id < 1152; id += 256) {
        int mo = id / 576, i = id - mo * 576;
        cpasync16(wbu[0] + (unsigned)(mo * 2304 + i * 4) * 4u,
                  wT + mo * 36864 + i * 4);
    }
    cpcommit();

    u64 acc[2][8];
    #pragma unroll
    for (int m = 0; m < 2; m++)
        #pragma unroll
        for (int j = 0; j < 8; j++) acc[m][j] = 0ull;

    for (int ci = 0; ci < 16; ci++) {
        cpwait0();
        __syncthreads();
        const float* cur = (ci & 1) ? wb1 : wb0;
        if (ci < 15) {
            unsigned dstb = wbu[(ci + 1) & 1];
            const float* srcb = wT + (ci + 1) * 2304;
            for (int id = tid; id < 1152; id += 256) {
                int mo = id / 576, i = id - mo * 576;
                cpasync16(dstb + (unsigned)(mo * 2304 + i * 4) * 4u,
                          srcb + mo * 36864 + i * 4);
            }
        }
        cpcommit();
        #pragma unroll
        for (int lc = 0; lc < 4; lc++) {
            const float* ib = ism + (ci * 4 + lc) * 120 + grp * 20;
            #pragma unroll
            for (int ky = 0; ky < 3; ky++) {
                const ulonglong2* P = (const ulonglong2*)(ib + ky * 20);
                ulonglong2 pa = P[0], pb = P[1], pc = P[2], pd = P[3], pe = P[4];
                u64 p[10] = {pa.x, pa.y, pb.x, pb.y, pc.x, pc.y, pd.x, pd.y, pe.x, pe.y};
                #pragma unroll
                for (int m = 0; m < 2; m++) {
                    const float* wp = cur + m * 2304 + (lc * 9 + ky * 3) * 64 + oc;
                    u64 w0 = bc2(wp[0]), w1 = bc2(wp[64]), w2 = bc2(wp[128]);
                    #pragma unroll
                    for (int j = 0; j < 8; j++) {
                        fma2(acc[m][j], w0, p[j]);
                        fma2(acc[m][j], w1, p[j + 1]);
                        fma2(acc[m][j], w2, p[j + 2]);
                    }
                }
            }
        }
    }

    float res[16];
    #pragma unroll
    for (int xx = 0; xx < 16; xx++) res[xx] = 0.f;
    #pragma unroll
    for (int m = 0; m < 2; m++) {
        float sv = s[((size_t)cls * 6 + 3 + m) * 64 + oc];
        float bv = b[((size_t)cls * 6 + 3 + m) * 64 + oc];
        #pragma unroll
        for (int j = 0; j < 8; j++) {
            float2 v = upk(acc[m][j]);
            res[j]     += fminf(fmaxf(v.x * sv + bv, 0.f), 6.f);
            res[j + 8] += fminf(fmaxf(v.y * sv + bv, 0.f), 6.f);
        }
    }
    __syncthreads();
    float* osm = wb0;   // 64*65 = 4160 <= 4608 ✓
    #pragma unroll
    for (int xx = 0; xx < 16; xx++) osm[oc * 65 + grp * 16 + xx] = res[xx];
    __syncthreads();
    for (int id = tid; id < 1024; id += 256) {
        int oc2 = id >> 4, rq = id & 15, r = rq >> 2, qx = rq & 3;
        const float* sp = osm + oc2 * 65 + r * 16 + qx * 4;
        float4 v = {sp[0], sp[1], sp[2], sp[3]};
        *(float4*)(dst + (size_t)oc2 * HWSZ + (ty0 + r) * HH + tx0 + qx * 4) = v;
    }
}

// ---------------------------------------------------------------------------
// K5 (fused, R12 exact): x33 conv3x3 in-block + concat 1x1-BN + residual.
// ---------------------------------------------------------------------------
__global__ __launch_bounds__(256, 3)
void k_outf(const float* __restrict__ s, const float* __restrict__ b,
            const float* __restrict__ catw, const float* __restrict__ cats,
            const float* __restrict__ catb, float* __restrict__ out) {
    int cls = blockIdx.z;
    int tx0 = blockIdx.x * 16, ty0 = blockIdx.y * 4;
    size_t cbase = (size_t)cls * CN * HWSZ;
    const float* x223 = g_x223 + cbase;
    const float* x112 = g_x112 + cbase;
    extern __shared__ float sm[];
    float* ism  = sm;            // 7680
    float* wbuf = ism + 7680;    // 2304
    float* x1sm = wbuf + 2304;   // 4096
    float* x3sm = x1sm + 4096;   // 4224
    unsigned smb = (unsigned)__cvta_generic_to_shared(sm);
    unsigned wbu[2] = { smb + 7680u * 4u, smb + (7680u + 1152u) * 4u };
    int tid = threadIdx.x;
    int oc = tid & 63, grp = tid >> 6;
    const float* wT = g_wT + (size_t)(cls * 6 + 5) * 576 * 64;

    for (int id = tid; id < 288; id += 256)
        cpasync16(wbu[0] + (unsigned)id * 16u, wT + id * 4);
    cpcommit();

    for (int id = tid; id < 7680; id += 256) {
        int c = id / 120, rem = id - c * 120;
        int r = rem / 20, p = rem - r * 20;
        int gy = ty0 + r - 1, gx = tx0 + (p >> 1) + 8 * (p & 1) - 1;
        float v = 0.f;
        if ((unsigned)gy < 256u && (unsigned)gx < 256u)
            v = x223[(size_t)c * HWSZ + gy * HH + gx];
        ism[id] = v;
    }
    for (int id = tid; id < 4096; id += 256) {
        int c = id >> 6, px = id & 63, row = px >> 4, pp = px & 15;
        int col = (pp >> 1) + 8 * (pp & 1);
        x1sm[id] = x112[(size_t)c * HWSZ + (ty0 + row) * HH + tx0 + col];
    }

    u64 acc[8];
    #pragma unroll
    for (int j = 0; j < 8; j++) acc[j] = 0ull;
    for (int ci = 0; ci < 32; ci++) {
        cpwait0();
        __syncthreads();
        const float* cur = wbuf + (ci & 1) * 1152;
        if (ci < 31) {
            unsigned dstb = wbu[(ci + 1) & 1];
            const float* srcb = wT + (ci + 1) * 1152;
            for (int id = tid; id < 288; id += 256)
                cpasync16(dstb + (unsigned)id * 16u, srcb + id * 4);
        }
        cpcommit();
        #pragma unroll
        for (int c = 0; c < 2; c++) {
            const float* ib = ism + (ci * 2 + c) * 120 + grp * 20;
            #pragma unroll
            for (int ky = 0; ky < 3; ky++) {
                const ulonglong2* P = (const ulonglong2*)(ib + ky * 20);
                ulonglong2 pa = P[0], pb = P[1], pc = P[2], pd = P[3], pe = P[4];
                u64 p[10] = {pa.x, pa.y, pb.x, pb.y, pc.x, pc.y, pd.x, pd.y, pe.x, pe.y};
                const float* wp = cur + (c * 9 + ky * 3) * 64 + oc;
                u64 w0 = bc2(wp[0]), w1 = bc2(wp[64]), w2 = bc2(wp[128]);
                #pragma unroll
                for (int j = 0; j < 8; j++) {
                    fma2(acc[j], w0, p[j]);
                    fma2(acc[j], w1, p[j + 1]);
                    fma2(acc[j], w2, p[j + 2]);
                }
            }
        }
    }
    {
        float sv = s[((size_t)cls * 6 + 5) * 64 + oc];
        float bv = b[((size_t)cls * 6 + 5) * 64 + oc];
        #pragma unroll
        for (int j = 0; j < 8; j++) {
            float2 v = upk(acc[j]);
            x3sm[oc * 66 + grp * 16 + 2 * j]     = fminf(fmaxf(v.x * sv + bv, 0.f), 6.f);
            x3sm[oc * 66 + grp * 16 + 2 * j + 1] = fminf(fmaxf(v.y * sv + bv, 0.f), 6.f);
        }
    }

    int ocp = tid >> 3, seg = tid & 7;
    int row = seg >> 1, pj0 = (seg & 1) * 4;
    u64 y[2][4];
    #pragma unroll
    for (int r = 0; r < 2; r++)
        #pragma unroll
        for (int k = 0; k < 4; k++) y[r][k] = 0ull;
    const float* cwb = catw + (size_t)cls * 64 * 192;

    #pragma unroll
    for (int sidx = 0; sidx < 3; sidx++) {
        #pragma unroll
        for (int half = 0; half < 2; half++) {
            __syncthreads();
            for (int id = tid; id < 2048; id += 256) {
                int o2 = id >> 5, c = id & 31;
                wbuf[o2 * 33 + c] = cwb[o2 * 192 + sidx * 64 + half * 32 + c];
            }
            __syncthreads();
            const float* w0r = wbuf + (2 * ocp) * 33;
            const float* w1r = wbuf + (2 * ocp + 1) * 33;
            #pragma unroll 4
            for (int c = 0; c < 32; c++) {
                int cg = half * 32 + c;
                u64 wa = bc2(w0r[c]);
                u64 wb2 = bc2(w1r[c]);
                const u64* xp;
                if (sidx == 0)      xp = (const u64*)(x1sm + cg * 64 + row * 16 + 2 * pj0);
                else if (sidx == 1) xp = (const u64*)(ism + cg * 120 + (row + 1) * 20 + 2 * (pj0 + 1));
                else                xp = (const u64*)(x3sm + cg * 66 + row * 16 + 2 * pj0);
                #pragma unroll
                for (int k = 0; k < 4; k++) {
                    u64 v = xp[k];
                    fma2(y[0][k], wa,  v);
                    fma2(y[1][k], wb2, v);
                }
            }
        }
    }

    const float* o1 = g_out1 + cbase;
    float* ob = out + ((size_t)cls * CN) * HWSZ;
    #pragma unroll
    for (int rr = 0; rr < 2; rr++) {
        int o2 = 2 * ocp + rr;
        float csv = cats[cls * 64 + o2], cbv = catb[cls * 64 + o2];
        float lo[4], hi[4];
        #pragma unroll
        for (int k = 0; k < 4; k++) {
            float2 t = upk(y[rr][k]);
            lo[k] = t.x * csv + cbv;
            hi[k] = t.y * csv + cbv;
        }
        const float* rp = o1 + (size_t)o2 * HWSZ + (ty0 + row) * HH + tx0 + pj0;
        float4 ra = *(const float4*)rp;
        float4 rb = *(const float4*)(rp + 8);
        float4 oa, obv;
        oa.x = fmaxf(lo[0] + ra.x, 0.f);
        oa.y = fmaxf(lo[1] + ra.y, 0.f);
        oa.z = fmaxf(lo[2] + ra.z, 0.f);
        oa.w = fmaxf(lo[3] + ra.w, 0.f);
        obv.x = fmaxf(hi[0] + rb.x, 0.f);
        obv.y = fmaxf(hi[1] + rb.y, 0.f);
        obv.z = fmaxf(hi[2] + rb.z, 0.f);
        obv.w = fmaxf(hi[3] + rb.w, 0.f);
        float* op = ob + (size_t)o2 * HWSZ + (ty0 + row) * HH + tx0 + pj0;
        *(float4*)op = oa;
        *(float4*)(op + 8) = obv;
    }
}

// ---------------------------------------------------------------------------
extern "C" void kernel_launch(void* const* d_in, const int* in_sizes, int n_in,
                              void* d_out, int out_size) {
    const float* x    = (const float*)d_in[0];
    const float* qkw  = (const float*)d_in[1];
    const float* qks  = (const float*)d_in[2];
    const float* qkb  = (const float*)d_in[3];
    const float* relb = (const float*)d_in[4];
    const float* wvw  = (const float*)d_in[5];
    const float* wvs  = (const float*)d_in[6];
    const float* wvb  = (const float*)d_in[7];
    const float* mmsw = (const float*)d_in[8];
    const float* mmss = (const float*)d_in[9];
    const float* mmsb = (const float*)d_in[10];
    const float* catw = (const float*)d_in[11];
    const float* cats = (const float*)d_in[12];
    const float* catb = (const float*)d_in[13];
    float* out = (float*)d_out;

    const int SM_MASK = (4096 + 4160 + 8320 + 64 + 900) * 4;          // 70160
    const int SM_ATTN = (4096 + 4096 + 4160 + 4160 + 900 + 64) * 4;   // 69904
    const int SM_C3   = (4608 + 2 * 3 * 2304) * 4;                    // 73728
    const int SM_C2W  = (7680 + 2 * 2 * 2304) * 4;                    // 67584
    const int SM_OUTF = (7680 + 2304 + 4096 + 4224) * 4;              // 73216

    cudaFuncSetAttribute(k_mask, cudaFuncAttributeMaxDynamicSharedMemorySize, SM_MASK);
    cudaFuncSetAttribute(k_attn, cudaFuncAttributeMaxDynamicSharedMemorySize, SM_ATTN);
    cudaFuncSetAttribute((const void*)k_conv3<3,3>, cudaFuncAttributeMaxDynamicSharedMemorySize, SM_C3);
    cudaFuncSetAttribute(k_conv3w, cudaFuncAttributeMaxDynamicSharedMemorySize, SM_C2W);
    cudaFuncSetAttribute(k_outf, cudaFuncAttributeMaxDynamicSharedMemorySize, SM_OUTF);

    k_prep<<<(NCLS * 6 * 64 * 576 + 255) / 256, 256>>>(mmsw);
    k_mask<<<dim3(NWIN, NCLS), 256, SM_MASK>>>(x, qkw, qks, qkb, relb);
    k_attn<<<dim3(NWIN, NCLS), 256, SM_ATTN>>>(x, relb, wvw, wvs, wvb);
    dim3 cg(32, 64, NCLS);
    k_conv3<3,3><<<cg, 256, SM_C3>>>(0, 1, mmss, mmsb, 0);
    dim3 cw(16, 64, NCLS);
    k_conv3w<<<cw, 256, SM_C2W>>>(mmss, mmsb);
    dim3 og(16, 64, NCLS);
    k_outf<<<og, 256, SM_OUTF>>>(mmss, mmsb, catw, cats, catb, out);
}